// round 9
// baseline (speedup 1.0000x reference)
#include <cuda_runtime.h>

// Fixed shapes: B=64, P=68, H=W=64 -> 4352 tiles of 4096 pixels
#define HW       4096
#define NTHREADS 256
#define NWARPS   8
#define EPS      1e-5f
#define LOG2E    1.4426950408889634f
#define LN2      0.6931471805599453f

// Raw MUFU intrinsics (exp2f/log2f are PRECISE libm without -use_fast_math)
__device__ __forceinline__ float ex2(float x) {
    float r; asm("ex2.approx.ftz.f32 %0, %1;" : "=f"(r) : "f"(x)); return r;
}
__device__ __forceinline__ float lg2(float x) {
    float r; asm("lg2.approx.f32 %0, %1;" : "=f"(r) : "f"(x)); return r;
}
__device__ __forceinline__ void cp_async16(void* smem_dst, const void* gmem_src) {
    unsigned s = (unsigned)__cvta_generic_to_shared(smem_dst);
    asm volatile("cp.async.cg.shared.global [%0], [%1], 16;" :: "r"(s), "l"(gmem_src));
}

// Cross-block accumulator: zero at entry; last block restores zero (graph-replay safe).
__device__ float        g_partial = 0.0f;
__device__ unsigned int g_count   = 0u;

__global__ __launch_bounds__(NTHREADS, 6)
void gauss_kl_kernel(const float* __restrict__ hm,
                     const float* __restrict__ means,
                     const float* __restrict__ cov,
                     float* __restrict__ out,
                     float inv_rows)
{
    __shared__ float4 sh[HW / 4];          // 16KB heatmap tile
    __shared__ float  ws[NWARPS];
    __shared__ float  wa[NWARPS];

    const int bp  = blockIdx.x;
    const int tid = threadIdx.x;

    // Stream the tile into smem immediately — bypasses the register file,
    // so the 16 heatmap values cost ZERO registers across the barrier.
    {
        const float4* g = (const float4*)(hm + (size_t)bp * HW);
#pragma unroll
        for (int k = 0; k < 4; k++)
            cp_async16(&sh[tid + k * NTHREADS], g + tid + k * NTHREADS);
        asm volatile("cp.async.commit_group;");
    }

    // Per-tile Gaussian parameters
    const float mx  = __ldg(&means[bp * 2 + 0]);
    const float my  = __ldg(&means[bp * 2 + 1]);
    const float s00 = __ldg(&cov[bp * 4 + 0]);
    const float s01 = __ldg(&cov[bp * 4 + 1]);
    const float s10 = __ldg(&cov[bp * 4 + 2]);
    const float s11 = __ldg(&cov[bp * 4 + 3]);
    const float det = fmaf(s00, s11, -s01 * s10) + EPS;
    const float inv_det = LOG2E / det;
    // lp2 = log2(exp(-quad/2)) = Ac*dx^2 + Bc*dx*dy + Cc*dy^2
    const float Ac = -0.5f * s11 * inv_det;
    const float Bc =  0.5f * (s01 + s10) * inv_det;
    const float Cc = -0.5f * s00 * inv_det;

    // Geometry: i4 = tid + 256k -> row = (tid>>4) + 16k, x0 = (tid&15)*4
    const float xm  = (float)((tid & 15) << 2) - mx;
    const float dx0 = xm,        dx1 = xm + 1.0f;
    const float dx2 = xm + 2.0f, dx3 = xm + 3.0f;
    const float dyb = (float)(tid >> 4) - my;

    // Pass 1: e = 2^lp2 (EX2), S = pairwise sum
    float e[16];
    float S = 0.0f;
#pragma unroll
    for (int k = 0; k < 4; k++) {
        const float dy   = dyb + (float)(16 * k);
        const float bdy  = Bc * dy;
        const float cdy2 = (Cc * dy) * dy;
        const float e0 = ex2(fmaf(fmaf(Ac, dx0, bdy), dx0, cdy2));
        const float e1 = ex2(fmaf(fmaf(Ac, dx1, bdy), dx1, cdy2));
        const float e2 = ex2(fmaf(fmaf(Ac, dx2, bdy), dx2, cdy2));
        const float e3 = ex2(fmaf(fmaf(Ac, dx3, bdy), dx3, cdy2));
        e[4*k+0] = e0; e[4*k+1] = e1; e[4*k+2] = e2; e[4*k+3] = e3;
        S += (e0 + e1) + (e2 + e3);
    }

    // Reduce S: warp shfl, lane0 -> smem, ONE barrier, all threads sum partials
    const int wid = tid >> 5, lid = tid & 31;
#pragma unroll
    for (int o = 16; o > 0; o >>= 1) S += __shfl_xor_sync(0xffffffffu, S, o);
    if (lid == 0) ws[wid] = S;
    __syncthreads();
    const float Sfull = ((ws[0] + ws[1]) + (ws[2] + ws[3]))
                      + ((ws[4] + ws[5]) + (ws[6] + ws[7]));
    const float c = EPS * Sfull;                 // pr + eps = (e + c)/S

    // Each thread reads back ONLY the bytes it copied -> per-thread wait is enough.
    asm volatile("cp.async.wait_group 0;");

    // Pass 2: acc = sum hm * (lg2(hm) - lg2(e + c))   (heatmap from smem)
    float acc = 0.0f;
#pragma unroll
    for (int k = 0; k < 4; k++) {
        const float4 h = sh[tid + k * NTHREADS];
        acc = fmaf(h.x, lg2(h.x) - lg2(e[4*k+0] + c), acc);
        acc = fmaf(h.y, lg2(h.y) - lg2(e[4*k+1] + c), acc);
        acc = fmaf(h.z, lg2(h.z) - lg2(e[4*k+2] + c), acc);
        acc = fmaf(h.w, lg2(h.w) - lg2(e[4*k+3] + c), acc);
    }

    // Reduce acc; tid0 adds tile value into device scratch (no memset launch)
#pragma unroll
    for (int o = 16; o > 0; o >>= 1) acc += __shfl_xor_sync(0xffffffffu, acc, o);
    if (lid == 0) wa[wid] = acc;
    __syncthreads();
    if (tid == 0) {
        const float v = ((wa[0] + wa[1]) + (wa[2] + wa[3]))
                      + ((wa[4] + wa[5]) + (wa[6] + wa[7]));
        // loss_tile = ln2 * (acc + lg2(S))   [sum(hm) == 1 per tile]
        const float tile = (LN2 * inv_rows) * (v + lg2(Sfull));
        atomicAdd(&g_partial, tile);
        __threadfence();
        const unsigned old = atomicAdd(&g_count, 1u);
        if (old == gridDim.x - 1) {          // last block finalizes + resets
            __threadfence();
            out[0]    = g_partial;
            g_partial = 0.0f;
            g_count   = 0u;
        }
    }
}

extern "C" void kernel_launch(void* const* d_in, const int* in_sizes, int n_in,
                              void* d_out, int out_size)
{
    const float* hm    = (const float*)d_in[0];   // [B,P,H,W]
    const float* means = (const float*)d_in[1];   // [B,P,2]
    const float* cov   = (const float*)d_in[2];   // [B,P,4]
    float* out = (float*)d_out;

    const int n_bp = in_sizes[1] / 2;             // 4352

    gauss_kl_kernel<<<n_bp, NTHREADS>>>(hm, means, cov, out, 1.0f / (float)n_bp);
}

// round 10
// speedup vs baseline: 1.0137x; 1.0137x over previous
#include <cuda_runtime.h>

// Fixed shapes: B=64, P=68, H=W=64 -> 4352 tiles of 4096 pixels
#define HW       4096
#define NTHREADS 256
#define NWARPS   8
#define EPS      1e-5f
#define LOG2E    1.4426950408889634f
#define LN2      0.6931471805599453f
// Deep-tail threshold on lp = log2(prob-kernel). Safe: S >= 0.83 =>
// lg2(c) >= -16.9, so lp < -30 => |lg2(e+c)-lg2(c)| < 1.6e-4 bits and
// e's contribution to S < 1e-5 relative.
#define LP_TAIL  (-30.0f)

__device__ __forceinline__ float ex2(float x) {
    float r; asm("ex2.approx.ftz.f32 %0, %1;" : "=f"(r) : "f"(x)); return r;
}
__device__ __forceinline__ float lg2(float x) {
    float r; asm("lg2.approx.f32 %0, %1;" : "=f"(r) : "f"(x)); return r;
}

// Cross-block accumulator: zero at entry; last block restores zero (replay-safe).
__device__ float        g_partial = 0.0f;
__device__ unsigned int g_count   = 0u;

__global__ __launch_bounds__(NTHREADS)
void gauss_kl_kernel(const float* __restrict__ hm,
                     const float* __restrict__ means,
                     const float* __restrict__ cov,
                     float* __restrict__ out,
                     float inv_rows)
{
    const int bp  = blockIdx.x;
    const int tid = threadIdx.x;

    // Front-batch the 4 streaming LDG.128 loads (latency hidden under pass 1)
    const float4* hm4 = reinterpret_cast<const float4*>(hm + (size_t)bp * HW);
    float4 h[4];
#pragma unroll
    for (int k = 0; k < 4; k++) h[k] = __ldcs(&hm4[tid + k * NTHREADS]);

    // Per-tile Gaussian parameters
    const float mx  = __ldg(&means[bp * 2 + 0]);
    const float my  = __ldg(&means[bp * 2 + 1]);
    const float s00 = __ldg(&cov[bp * 4 + 0]);
    const float s01 = __ldg(&cov[bp * 4 + 1]);
    const float s10 = __ldg(&cov[bp * 4 + 2]);
    const float s11 = __ldg(&cov[bp * 4 + 3]);
    const float det = fmaf(s00, s11, -s01 * s10) + EPS;
    const float inv_det = LOG2E / det;
    // lp = log2(exp(-quad/2)) = Ac*dx^2 + Bc*dx*dy + Cc*dy^2   (<= 0)
    const float Ac = -0.5f * s11 * inv_det;
    const float Bc =  0.5f * (s01 + s10) * inv_det;
    const float Cc = -0.5f * s00 * inv_det;

    // Geometry: i4 = tid + 256k -> row = (tid>>4) + 16k, x0 = (tid&15)*4
    const float xm  = (float)((tid & 15) << 2) - mx;
    const float dx0 = xm,        dx1 = xm + 1.0f;
    const float dx2 = xm + 2.0f, dx3 = xm + 3.0f;
    const float dyb = (float)(tid >> 4) - my;

    // Pass 1: lp per pixel; warp-uniform deep-tail skip of EX2
    float e[16];
    unsigned live_flags = 0u;   // bit k set -> k-group has a live lane in warp
    float S = 0.0f;
#pragma unroll
    for (int k = 0; k < 4; k++) {
        const float dy   = dyb + (float)(16 * k);
        const float bdy  = Bc * dy;
        const float cdy2 = (Cc * dy) * dy;
        const float l0 = fmaf(fmaf(Ac, dx0, bdy), dx0, cdy2);
        const float l1 = fmaf(fmaf(Ac, dx1, bdy), dx1, cdy2);
        const float l2 = fmaf(fmaf(Ac, dx2, bdy), dx2, cdy2);
        const float l3 = fmaf(fmaf(Ac, dx3, bdy), dx3, cdy2);
        const float lmax = fmaxf(fmaxf(l0, l1), fmaxf(l2, l3));
        if (__any_sync(0xffffffffu, lmax > LP_TAIL)) {
            live_flags |= (1u << k);
            const float e0 = ex2(l0), e1 = ex2(l1);
            const float e2 = ex2(l2), e3 = ex2(l3);
            e[4*k+0] = e0; e[4*k+1] = e1; e[4*k+2] = e2; e[4*k+3] = e3;
            S += (e0 + e1) + (e2 + e3);
        }
        // deep tail: e contributes < 2^-30 each to S and never read in pass 2
    }

    // Reduce S: warp shfl, lane0 -> smem, ONE barrier, all threads sum partials
    __shared__ float ws[NWARPS];
    __shared__ float wa[NWARPS];
    const int wid = tid >> 5, lid = tid & 31;
#pragma unroll
    for (int o = 16; o > 0; o >>= 1) S += __shfl_xor_sync(0xffffffffu, S, o);
    if (lid == 0) ws[wid] = S;
    __syncthreads();
    const float Sfull = ((ws[0] + ws[1]) + (ws[2] + ws[3]))
                      + ((ws[4] + ws[5]) + (ws[6] + ws[7]));
    const float c   = EPS * Sfull;              // pr + eps = (e + c)/S
    const float lgc = lg2(c);

    // Pass 2: acc = sum hm * (lg2(hm) - lg2(e + c));
    // tail k-groups use lg2(c) directly (saves 4 LG2 per warp per group)
    float acc = 0.0f;
#pragma unroll
    for (int k = 0; k < 4; k++) {
        const float4 hv = h[k];
        if (live_flags & (1u << k)) {
            acc = fmaf(hv.x, lg2(hv.x) - lg2(e[4*k+0] + c), acc);
            acc = fmaf(hv.y, lg2(hv.y) - lg2(e[4*k+1] + c), acc);
            acc = fmaf(hv.z, lg2(hv.z) - lg2(e[4*k+2] + c), acc);
            acc = fmaf(hv.w, lg2(hv.w) - lg2(e[4*k+3] + c), acc);
        } else {
            acc = fmaf(hv.x, lg2(hv.x) - lgc, acc);
            acc = fmaf(hv.y, lg2(hv.y) - lgc, acc);
            acc = fmaf(hv.z, lg2(hv.z) - lgc, acc);
            acc = fmaf(hv.w, lg2(hv.w) - lgc, acc);
        }
    }

    // Reduce acc; tid0 adds tile value into device scratch (no memset launch)
#pragma unroll
    for (int o = 16; o > 0; o >>= 1) acc += __shfl_xor_sync(0xffffffffu, acc, o);
    if (lid == 0) wa[wid] = acc;
    __syncthreads();
    if (tid == 0) {
        const float v = ((wa[0] + wa[1]) + (wa[2] + wa[3]))
                      + ((wa[4] + wa[5]) + (wa[6] + wa[7]));
        // loss_tile = ln2 * (acc + lg2(S))   [sum(hm) == 1 per tile]
        const float tile = (LN2 * inv_rows) * (v + lg2(Sfull));
        atomicAdd(&g_partial, tile);
        __threadfence();
        const unsigned old = atomicAdd(&g_count, 1u);
        if (old == gridDim.x - 1) {          // last block finalizes + resets
            __threadfence();
            out[0]    = g_partial;
            g_partial = 0.0f;
            g_count   = 0u;
        }
    }
}

extern "C" void kernel_launch(void* const* d_in, const int* in_sizes, int n_in,
                              void* d_out, int out_size)
{
    const float* hm    = (const float*)d_in[0];   // [B,P,H,W]
    const float* means = (const float*)d_in[1];   // [B,P,2]
    const float* cov   = (const float*)d_in[2];   // [B,P,4]
    float* out = (float*)d_out;

    const int n_bp = in_sizes[1] / 2;             // 4352

    gauss_kl_kernel<<<n_bp, NTHREADS>>>(hm, means, cov, out, 1.0f / (float)n_bp);
}